// round 1
// baseline (speedup 1.0000x reference)
#include <cuda_runtime.h>
#include <math.h>

// Problem: B=512, N=128, F=128, K=4
// Inputs: H, E, RW1, SW1, RW2, SW2, RW3, SW3, W1, b1, W2, b2

// ---------------- scratch (device globals; no allocs allowed) ----------------
__device__ float g_Wcat[128 * 640];          // per-layer repacked [m, k*128+n | 512+l]
__device__ float g_G[512 * 128 * 512];       // [b, j, k*128+n]  (134 MB)
__device__ float g_S[512 * 128 * 128];       // [b, i, l]
__device__ float g_Ha[512 * 128 * 128];      // layer ping
__device__ float g_Hb[512 * 128 * 128];      // layer pong
__device__ float g_D[512 * 128];
__device__ float g_partial[1024];

// ---------------- D = 1 / (rowsum(E) + K) ----------------
__global__ void dsum_kernel(const float* __restrict__ E) {
    int gwarp = (blockIdx.x * blockDim.x + threadIdx.x) >> 5;  // row index (b*128+i)
    int lane = threadIdx.x & 31;
    if (gwarp >= 512 * 128) return;
    const float4* row = (const float4*)(E + (size_t)gwarp * 512);
    float s = 0.f;
#pragma unroll
    for (int i = 0; i < 4; i++) {
        float4 v = row[lane + 32 * i];
        s += v.x + v.y + v.z + v.w;
    }
#pragma unroll
    for (int o = 16; o; o >>= 1) s += __shfl_down_sync(0xffffffffu, s, o);
    if (lane == 0) g_D[gwarp] = 1.0f / (s + 4.0f);
}

// ---------------- repack RW[m,n,k] + SW[m,l] -> Wcat[m, 640] ----------------
__global__ void repack_kernel(const float* __restrict__ RW, const float* __restrict__ SW) {
    int idx = blockIdx.x * blockDim.x + threadIdx.x;
    if (idx >= 128 * 640) return;
    int m = idx / 640, c = idx % 640;
    float v;
    if (c < 512) {
        int k = c >> 7, n = c & 127;
        v = RW[(m * 128 + n) * 4 + k];
    } else {
        v = SW[m * 128 + (c - 512)];
    }
    g_Wcat[idx] = v;
}

// ---------------- tiled SGEMM: 128x128 CTA tile, 8x8 per thread ----------------
// MODE 0: C[b] = Hin[b](128x128) @ Wcat(128x640), store into g_G / g_S
// MODE 1: msg[b] = E[b](128x512) @ g_G[b](512x128), epilogue sigmoid(msg*D + S)
template <int MODE>
__global__ __launch_bounds__(256, 2) void gemm_kernel(const float* __restrict__ Eptr,
                                                      const float* __restrict__ Hext,
                                                      int sel) {
    constexpr int K   = (MODE == 0) ? 128 : 512;
    constexpr int LDA = (MODE == 0) ? 128 : 512;
    constexpr int LDB = (MODE == 0) ? 640 : 128;

    int b = blockIdx.z;
    int colTile = blockIdx.x * 128;

    const float* A;
    const float* Bm;
    if (MODE == 0) {
        const float* Hin = (sel == 0) ? Hext : ((sel == 1) ? g_Ha : g_Hb);
        A = Hin + (size_t)b * 16384;
        Bm = g_Wcat;
    } else {
        A = Eptr + (size_t)b * 65536;
        Bm = g_G + (size_t)b * 65536;
    }

    __shared__ float As[16][129];
    __shared__ float Bs[16][128];

    int tid = threadIdx.x;
    int tx = tid & 15, ty = tid >> 4;

    float acc[8][8];
#pragma unroll
    for (int i = 0; i < 8; i++)
#pragma unroll
        for (int j = 0; j < 8; j++) acc[i][j] = 0.f;

    for (int kk = 0; kk < K; kk += 16) {
        // load A tile (128 rows x 16 cols), stored transposed As[k][row]
#pragma unroll
        for (int it = 0; it < 2; it++) {
            int e = tid + it * 256;
            int arow = e >> 2;
            int ac = (e & 3) << 2;
            float4 av = *(const float4*)(A + (size_t)arow * LDA + kk + ac);
            As[ac + 0][arow] = av.x;
            As[ac + 1][arow] = av.y;
            As[ac + 2][arow] = av.z;
            As[ac + 3][arow] = av.w;
            // load B tile (16 rows x 128 cols)
            int brow = e >> 5;
            int bc = (e & 31) << 2;
            float4 bv = *(const float4*)(Bm + (size_t)(kk + brow) * LDB + colTile + bc);
            *(float4*)&Bs[brow][bc] = bv;
        }
        __syncthreads();

#pragma unroll
        for (int kq = 0; kq < 16; kq++) {
            float af[8];
#pragma unroll
            for (int i = 0; i < 8; i++) af[i] = As[kq][ty * 8 + i];
            float4 b0 = *(float4*)&Bs[kq][tx * 8];
            float4 b1 = *(float4*)&Bs[kq][tx * 8 + 4];
            float bf[8] = {b0.x, b0.y, b0.z, b0.w, b1.x, b1.y, b1.z, b1.w};
#pragma unroll
            for (int i = 0; i < 8; i++)
#pragma unroll
                for (int j = 0; j < 8; j++) acc[i][j] += af[i] * bf[j];
        }
        __syncthreads();
    }

    int row0 = ty * 8;
    int col0 = colTile + tx * 8;

    if (MODE == 0) {
        if (colTile < 512) {
            float* out = g_G + (size_t)b * 65536;
#pragma unroll
            for (int i = 0; i < 8; i++) {
                float* o = out + (size_t)(row0 + i) * 512 + col0;
#pragma unroll
                for (int j = 0; j < 8; j += 4) {
                    float4 v = make_float4(acc[i][j], acc[i][j + 1], acc[i][j + 2], acc[i][j + 3]);
                    *(float4*)(o + j) = v;
                }
            }
        } else {
            float* out = g_S + (size_t)b * 16384;
            int c0 = col0 - 512;
#pragma unroll
            for (int i = 0; i < 8; i++) {
                float* o = out + (size_t)(row0 + i) * 128 + c0;
#pragma unroll
                for (int j = 0; j < 8; j += 4) {
                    float4 v = make_float4(acc[i][j], acc[i][j + 1], acc[i][j + 2], acc[i][j + 3]);
                    *(float4*)(o + j) = v;
                }
            }
        }
    } else {
        float* Hout = ((sel == 1) ? g_Ha : g_Hb) + (size_t)b * 16384;
        const float* Sp = g_S + (size_t)b * 16384;
#pragma unroll
        for (int i = 0; i < 8; i++) {
            int r = row0 + i;
            float d = g_D[b * 128 + r];
#pragma unroll
            for (int j = 0; j < 8; j++) {
                int c = col0 + j;
                float v = acc[i][j] * d + Sp[r * 128 + c];
                Hout[r * 128 + c] = 1.0f / (1.0f + expf(-v));
            }
        }
    }
}

// ---------------- MLP head: LeakyReLU(H@W1+b1) @ W2 + b2 -> sigmoid -> partial sums ----------------
__global__ __launch_bounds__(128) void head_kernel(const float* __restrict__ W1,
                                                   const float* __restrict__ b1,
                                                   const float* __restrict__ W2,
                                                   const float* __restrict__ b2) {
    __shared__ float sH[64][129];
    __shared__ float sW1[128 * 20];
    __shared__ float sW2[20];
    __shared__ float sred[4];

    int tid = threadIdx.x;
    size_t base = (size_t)blockIdx.x * 64 * 128;
    const float* Hf = g_Ha;  // output of layer 3

    for (int i = tid; i < 64 * 128; i += 128) sH[i >> 7][i & 127] = Hf[base + i];
    for (int i = tid; i < 128 * 20; i += 128) sW1[i] = W1[i];
    if (tid < 20) sW2[tid] = W2[tid];
    __syncthreads();

    float s = 0.f;
    if (tid < 64) {
        float z[20];
#pragma unroll
        for (int c = 0; c < 20; c++) z[c] = b1[c];
        for (int m = 0; m < 128; m++) {
            float hv = sH[tid][m];
#pragma unroll
            for (int c = 0; c < 20; c++) z[c] += hv * sW1[m * 20 + c];
        }
        float a2 = b2[0];
#pragma unroll
        for (int c = 0; c < 20; c++) {
            float zz = z[c];
            float h = zz > 0.f ? zz : 0.1f * zz;
            a2 += h * sW2[c];
        }
        s = 1.0f / (1.0f + expf(-a2));
    }
#pragma unroll
    for (int o = 16; o; o >>= 1) s += __shfl_down_sync(0xffffffffu, s, o);
    if ((tid & 31) == 0) sred[tid >> 5] = s;
    __syncthreads();
    if (tid == 0) g_partial[blockIdx.x] = sred[0] + sred[1] + sred[2] + sred[3];
}

__global__ void reduce_kernel(float* __restrict__ out) {
    __shared__ float sred[32];
    int tid = threadIdx.x;  // 1024 threads, g_partial has 1024 entries
    float v = g_partial[tid];
#pragma unroll
    for (int o = 16; o; o >>= 1) v += __shfl_down_sync(0xffffffffu, v, o);
    if ((tid & 31) == 0) sred[tid >> 5] = v;
    __syncthreads();
    if (tid < 32) {
        float t = sred[tid];
#pragma unroll
        for (int o = 16; o; o >>= 1) t += __shfl_down_sync(0xffffffffu, t, o);
        if (tid == 0) out[0] = t * (1.0f / 65536.0f);
    }
}

// ---------------- launch ----------------
extern "C" void kernel_launch(void* const* d_in, const int* in_sizes, int n_in,
                              void* d_out, int out_size) {
    const float* H = (const float*)d_in[0];
    const float* E = (const float*)d_in[1];
    const float* RW[3] = {(const float*)d_in[2], (const float*)d_in[4], (const float*)d_in[6]};
    const float* SW[3] = {(const float*)d_in[3], (const float*)d_in[5], (const float*)d_in[7]};
    const float* W1 = (const float*)d_in[8];
    const float* b1 = (const float*)d_in[9];
    const float* W2 = (const float*)d_in[10];
    const float* b2 = (const float*)d_in[11];
    float* out = (float*)d_out;

    dsum_kernel<<<8192, 256>>>(E);

    // layer L: src sel (0=ext H, 1=g_Ha, 2=g_Hb), dst sel (1=g_Ha, 2=g_Hb)
    const int srcs[3] = {0, 1, 2};
    const int dsts[3] = {1, 2, 1};
    for (int L = 0; L < 3; L++) {
        repack_kernel<<<320, 256>>>(RW[L], SW[L]);
        gemm_kernel<0><<<dim3(5, 1, 512), 256>>>(E, H, srcs[L]);
        gemm_kernel<1><<<dim3(1, 1, 512), 256>>>(E, H, dsts[L]);
    }

    head_kernel<<<1024, 128>>>(W1, b1, W2, b2);
    reduce_kernel<<<1, 1024>>>(out);
}

// round 2
// speedup vs baseline: 2.5545x; 2.5545x over previous
#include <cuda_runtime.h>
#include <math.h>

// Problem: B=512, N=128, F=128, K=4
// Two-pass per layer, TF32 tensor cores:
//   pass0: G[b] = Hin[b](128x128) @ Wcat(128x640)  (cols 0..511 -> g_G, 512..639 -> g_S)
//   pass1: msg[b] = E[b](128x512) @ g_G[b](512x128); Hout = sigmoid(msg*D + S)

// ---------------- scratch ----------------
__device__ float g_Wcat[128 * 640];
__device__ float g_G[512 * 128 * 512];
__device__ float g_S[512 * 128 * 128];
__device__ float g_Ha[512 * 128 * 128];
__device__ float g_Hb[512 * 128 * 128];
__device__ float g_D[512 * 128];
__device__ float g_partial[1024];

// ---------------- helpers ----------------
__device__ __forceinline__ unsigned cvt_tf32(float x) {
    unsigned r;
    asm("cvt.rna.tf32.f32 %0, %1;" : "=r"(r) : "f"(x));
    return r;
}

__device__ __forceinline__ void mma_tf32(float* d, const unsigned* a, const unsigned* b) {
    asm volatile(
        "mma.sync.aligned.m16n8k8.row.col.f32.tf32.tf32.f32 "
        "{%0,%1,%2,%3},{%4,%5,%6,%7},{%8,%9},{%0,%1,%2,%3};"
        : "+f"(d[0]), "+f"(d[1]), "+f"(d[2]), "+f"(d[3])
        : "r"(a[0]), "r"(a[1]), "r"(a[2]), "r"(a[3]), "r"(b[0]), "r"(b[1]));
}

__device__ __forceinline__ void cp_async16(void* s, const void* g) {
    unsigned sa = (unsigned)__cvta_generic_to_shared(s);
    asm volatile("cp.async.cg.shared.global [%0], [%1], 16;" :: "r"(sa), "l"(g));
}

// ---------------- D = 1 / (rowsum(E) + K) ----------------
__global__ void dsum_kernel(const float* __restrict__ E) {
    int gwarp = (blockIdx.x * blockDim.x + threadIdx.x) >> 5;
    int lane = threadIdx.x & 31;
    if (gwarp >= 512 * 128) return;
    const float4* row = (const float4*)(E + (size_t)gwarp * 512);
    float s = 0.f;
#pragma unroll
    for (int i = 0; i < 4; i++) {
        float4 v = row[lane + 32 * i];
        s += v.x + v.y + v.z + v.w;
    }
#pragma unroll
    for (int o = 16; o; o >>= 1) s += __shfl_down_sync(0xffffffffu, s, o);
    if (lane == 0) g_D[gwarp] = 1.0f / (s + 4.0f);
}

// ---------------- repack RW[m,n,k] + SW[m,l] -> Wcat[m, 640] ----------------
__global__ void repack_kernel(const float* __restrict__ RW, const float* __restrict__ SW) {
    int idx = blockIdx.x * blockDim.x + threadIdx.x;
    if (idx >= 128 * 640) return;
    int m = idx / 640, c = idx % 640;
    float v;
    if (c < 512) {
        int k = c >> 7, n = c & 127;
        v = RW[(m * 128 + n) * 4 + k];
    } else {
        v = SW[m * 128 + (c - 512)];
    }
    g_Wcat[idx] = v;
}

// ---------------- TF32 tensor GEMM ----------------
// MODE 0: C[b] = Hin[b](128x128) @ Wcat(128x640)
// MODE 1: msg[b] = E[b](128x512) @ g_G[b](512x128), epilogue sigmoid(msg*D + S)
template <int MODE>
__global__ __launch_bounds__(256, 2) void gemm_tc(const float* __restrict__ Eptr,
                                                  const float* __restrict__ Hext,
                                                  int sel) {
    constexpr int KDIM = (MODE == 0) ? 128 : 512;
    constexpr int LDA  = (MODE == 0) ? 128 : 512;
    constexpr int LDB  = (MODE == 0) ? 640 : 128;
    constexpr int NK   = KDIM / 16;

    const int b = blockIdx.z;
    const int colTile = blockIdx.x * 128;

    const float* A;
    const float* Bm;
    if (MODE == 0) {
        const float* Hin = (sel == 0) ? Hext : ((sel == 1) ? g_Ha : g_Hb);
        A = Hin + (size_t)b * 16384;
        Bm = g_Wcat;
    } else {
        A = Eptr + (size_t)b * 65536;
        Bm = g_G + (size_t)b * 65536;
    }

    // A tile: 128 rows x 16 cols, row stride 20 (conflict-free for frag loads)
    // B tile: 16 rows x 128 cols, row stride 136
    __shared__ float As[2][128 * 20];
    __shared__ float Bs[2][16 * 136];

    const int tid = threadIdx.x;
    const int warp = tid >> 5, lane = tid & 31;
    const int wm = warp & 3, wn = warp >> 2;  // 4x2 warp grid
    const int lr = lane >> 2, lc = lane & 3;

    float acc[2][8][4];
#pragma unroll
    for (int mi = 0; mi < 2; mi++)
#pragma unroll
        for (int ni = 0; ni < 8; ni++)
#pragma unroll
            for (int q = 0; q < 4; q++) acc[mi][ni][q] = 0.f;

    // stage one KT=16 slab into buffer buf
    auto stage = [&](int kk, int buf) {
#pragma unroll
        for (int i = 0; i < 2; i++) {
            int f = tid + i * 256;           // 512 float4 for A
            int r = f >> 2, c = (f & 3) << 2;
            cp_async16(&As[buf][r * 20 + c], A + (size_t)r * LDA + kk + c);
        }
#pragma unroll
        for (int i = 0; i < 2; i++) {
            int f = tid + i * 256;           // 512 float4 for B
            int r = f >> 5, c = (f & 31) << 2;
            cp_async16(&Bs[buf][r * 136 + c], Bm + (size_t)(kk + r) * LDB + colTile + c);
        }
        asm volatile("cp.async.commit_group;");
    };

    stage(0, 0);
    for (int t = 0; t < NK; t++) {
        int buf = t & 1;
        if (t + 1 < NK) {
            stage((t + 1) * 16, buf ^ 1);
            asm volatile("cp.async.wait_group 1;");
        } else {
            asm volatile("cp.async.wait_group 0;");
        }
        __syncthreads();

        const float* Ab = As[buf];
        const float* Bb = Bs[buf];
#pragma unroll
        for (int kq = 0; kq < 2; kq++) {
            unsigned af[2][4];
#pragma unroll
            for (int mi = 0; mi < 2; mi++) {
                const float* ap = Ab + (wm * 32 + mi * 16 + lr) * 20 + kq * 8 + lc;
                af[mi][0] = cvt_tf32(ap[0]);
                af[mi][1] = cvt_tf32(ap[8 * 20]);
                af[mi][2] = cvt_tf32(ap[4]);
                af[mi][3] = cvt_tf32(ap[8 * 20 + 4]);
            }
#pragma unroll
            for (int ni = 0; ni < 8; ni++) {
                const float* bp = Bb + (kq * 8 + lc) * 136 + wn * 64 + ni * 8 + lr;
                unsigned bf[2];
                bf[0] = cvt_tf32(bp[0]);
                bf[1] = cvt_tf32(bp[4 * 136]);
                mma_tf32(acc[0][ni], af[0], bf);
                mma_tf32(acc[1][ni], af[1], bf);
            }
        }
        __syncthreads();
    }

    // ---- epilogue ----
    if (MODE == 0) {
#pragma unroll
        for (int mi = 0; mi < 2; mi++) {
            int r0 = wm * 32 + mi * 16 + lr;
#pragma unroll
            for (int ni = 0; ni < 8; ni++) {
                int cg = colTile + wn * 64 + ni * 8 + 2 * lc;
                float2 v0 = make_float2(acc[mi][ni][0], acc[mi][ni][1]);
                float2 v1 = make_float2(acc[mi][ni][2], acc[mi][ni][3]);
                if (cg < 512) {
                    float* o = g_G + (size_t)b * 65536;
                    *(float2*)(o + (size_t)r0 * 512 + cg) = v0;
                    *(float2*)(o + (size_t)(r0 + 8) * 512 + cg) = v1;
                } else {
                    float* o = g_S + (size_t)b * 16384;
                    *(float2*)(o + (size_t)r0 * 128 + (cg - 512)) = v0;
                    *(float2*)(o + (size_t)(r0 + 8) * 128 + (cg - 512)) = v1;
                }
            }
        }
    } else {
        const float* Sp = g_S + (size_t)b * 16384;
        float* Ho = ((sel == 1) ? g_Ha : g_Hb) + (size_t)b * 16384;
#pragma unroll
        for (int mi = 0; mi < 2; mi++) {
            int r0 = wm * 32 + mi * 16 + lr;
            float d0 = g_D[b * 128 + r0];
            float d1 = g_D[b * 128 + r0 + 8];
#pragma unroll
            for (int ni = 0; ni < 8; ni++) {
                int cg = wn * 64 + ni * 8 + 2 * lc;
                float2 s0 = *(const float2*)(Sp + (size_t)r0 * 128 + cg);
                float2 s1 = *(const float2*)(Sp + (size_t)(r0 + 8) * 128 + cg);
                float x0 = acc[mi][ni][0] * d0 + s0.x;
                float x1 = acc[mi][ni][1] * d0 + s0.y;
                float x2 = acc[mi][ni][2] * d1 + s1.x;
                float x3 = acc[mi][ni][3] * d1 + s1.y;
                float2 o0 = make_float2(1.0f / (1.0f + __expf(-x0)), 1.0f / (1.0f + __expf(-x1)));
                float2 o1 = make_float2(1.0f / (1.0f + __expf(-x2)), 1.0f / (1.0f + __expf(-x3)));
                *(float2*)(Ho + (size_t)r0 * 128 + cg) = o0;
                *(float2*)(Ho + (size_t)(r0 + 8) * 128 + cg) = o1;
            }
        }
    }
}

// ---------------- MLP head ----------------
__global__ __launch_bounds__(128) void head_kernel(const float* __restrict__ W1,
                                                   const float* __restrict__ b1,
                                                   const float* __restrict__ W2,
                                                   const float* __restrict__ b2) {
    __shared__ float sH[64][129];
    __shared__ float sW1[128 * 20];
    __shared__ float sW2[20];
    __shared__ float sred[4];

    int tid = threadIdx.x;
    size_t base = (size_t)blockIdx.x * 64 * 128;
    const float* Hf = g_Ha;  // output of layer 3

    for (int i = tid; i < 64 * 128; i += 128) sH[i >> 7][i & 127] = Hf[base + i];
    for (int i = tid; i < 128 * 20; i += 128) sW1[i] = W1[i];
    if (tid < 20) sW2[tid] = W2[tid];
    __syncthreads();

    float s = 0.f;
    if (tid < 64) {
        float z[20];
#pragma unroll
        for (int c = 0; c < 20; c++) z[c] = b1[c];
        for (int m = 0; m < 128; m++) {
            float hv = sH[tid][m];
#pragma unroll
            for (int c = 0; c < 20; c++) z[c] += hv * sW1[m * 20 + c];
        }
        float a2 = b2[0];
#pragma unroll
        for (int c = 0; c < 20; c++) {
            float zz = z[c];
            float h = zz > 0.f ? zz : 0.1f * zz;
            a2 += h * sW2[c];
        }
        s = 1.0f / (1.0f + expf(-a2));
    }
#pragma unroll
    for (int o = 16; o; o >>= 1) s += __shfl_down_sync(0xffffffffu, s, o);
    if ((tid & 31) == 0) sred[tid >> 5] = s;
    __syncthreads();
    if (tid == 0) g_partial[blockIdx.x] = sred[0] + sred[1] + sred[2] + sred[3];
}

__global__ void reduce_kernel(float* __restrict__ out) {
    __shared__ float sred[32];
    int tid = threadIdx.x;
    float v = g_partial[tid];
#pragma unroll
    for (int o = 16; o; o >>= 1) v += __shfl_down_sync(0xffffffffu, v, o);
    if ((tid & 31) == 0) sred[tid >> 5] = v;
    __syncthreads();
    if (tid < 32) {
        float t = sred[tid];
#pragma unroll
        for (int o = 16; o; o >>= 1) t += __shfl_down_sync(0xffffffffu, t, o);
        if (tid == 0) out[0] = t * (1.0f / 65536.0f);
    }
}

// ---------------- launch ----------------
extern "C" void kernel_launch(void* const* d_in, const int* in_sizes, int n_in,
                              void* d_out, int out_size) {
    const float* H = (const float*)d_in[0];
    const float* E = (const float*)d_in[1];
    const float* RW[3] = {(const float*)d_in[2], (const float*)d_in[4], (const float*)d_in[6]};
    const float* SW[3] = {(const float*)d_in[3], (const float*)d_in[5], (const float*)d_in[7]};
    const float* W1 = (const float*)d_in[8];
    const float* b1 = (const float*)d_in[9];
    const float* W2 = (const float*)d_in[10];
    const float* b2 = (const float*)d_in[11];
    float* out = (float*)d_out;

    dsum_kernel<<<8192, 256>>>(E);

    const int srcs[3] = {0, 1, 2};
    const int dsts[3] = {1, 2, 1};
    for (int L = 0; L < 3; L++) {
        repack_kernel<<<320, 256>>>(RW[L], SW[L]);
        gemm_tc<0><<<dim3(5, 1, 512), 256>>>(E, H, srcs[L]);
        gemm_tc<1><<<dim3(1, 1, 512), 256>>>(E, H, dsts[L]);
    }

    head_kernel<<<1024, 128>>>(W1, b1, W2, b2);
    reduce_kernel<<<1, 1024>>>(out);
}